// round 6
// baseline (speedup 1.0000x reference)
#include <cuda_runtime.h>
#include <cuda_bf16.h>
#include <cstddef>
#include <cstdint>

#define BB 2
#define SS 2048
#define DD 1024
#define NH 16

// Scratch
__device__ float g_K [(size_t)BB*SS*DD];   // K projection [4096][1024]
__device__ float g_W2[(size_t)BB*DD*DD];   // [2][1024][1024]
__device__ float g_M3[(size_t)BB*DD*DD];   // [2][1024][1024]  Wq @ W2
__device__ float g_B2[(size_t)BB*DD];      // combined bias per batch
__device__ float g_Y [(size_t)BB*SS*DD];   // pre-LN

// ---------------- helpers ----------------
__device__ __forceinline__ void ldm4(uint32_t* r, const unsigned short* p){
    uint32_t a=(uint32_t)__cvta_generic_to_shared(p);
    asm volatile("ldmatrix.sync.aligned.m8n8.x4.shared.b16 {%0,%1,%2,%3}, [%4];"
                 :"=r"(r[0]),"=r"(r[1]),"=r"(r[2]),"=r"(r[3]):"r"(a));
}
__device__ __forceinline__ void ldm4t(uint32_t* r, const unsigned short* p){
    uint32_t a=(uint32_t)__cvta_generic_to_shared(p);
    asm volatile("ldmatrix.sync.aligned.m8n8.x4.trans.shared.b16 {%0,%1,%2,%3}, [%4];"
                 :"=r"(r[0]),"=r"(r[1]),"=r"(r[2]),"=r"(r[3]):"r"(a));
}
__device__ __forceinline__ void mma16816(float* c, const uint32_t* a, uint32_t b0, uint32_t b1){
    asm volatile("mma.sync.aligned.m16n8k16.row.col.f32.bf16.bf16.f32 "
        "{%0,%1,%2,%3},{%4,%5,%6,%7},{%8,%9},{%0,%1,%2,%3};"
        : "+f"(c[0]),"+f"(c[1]),"+f"(c[2]),"+f"(c[3])
        : "r"(a[0]),"r"(a[1]),"r"(a[2]),"r"(a[3]),"r"(b0),"r"(b1));
}
__device__ __forceinline__ void split2(float x, float y, uint32_t& hi2, uint32_t& lo2){
    uint32_t ux=__float_as_uint(x)&0xffff0000u, uy=__float_as_uint(y)&0xffff0000u;
    hi2 = uy|(ux>>16);
    __nv_bfloat162 l=__floats2bfloat162_rn(x-__uint_as_float(ux), y-__uint_as_float(uy));
    lo2=*reinterpret_cast<uint32_t*>(&l);
}
__device__ __forceinline__ unsigned short bf16_bits(float f){
    __nv_bfloat16 b=__float2bfloat16(f); return *reinterpret_cast<unsigned short*>(&b);
}

// ---------------------------------------------------------------------------
// Unified bf16-split mma.sync GEMM, double-buffered smem.
// MODE 0: K  = x @ Wk + bk                (M=4096,N=1024,K=1024)
// MODE 1: W2[b,n] = Kslice^T @ wfc_slice  (M=64, N=1024, K=2048) x32
// MODE 3: M3[b] = Wq @ W2[b]              (M=1024,N=1024,K=1024) x2
// MODE 2: Y[b] = .125*x[b]@M3[b] + B2[b] + x[b]   (M=2048,N=1024,K=1024) x2
// ---------------------------------------------------------------------------
template<int MODE>
__global__ __launch_bounds__(256) void gemm_u(
    const float* __restrict__ A0, const float* __restrict__ B0,
    float* __restrict__ C0, const float* __restrict__ bias,
    const float* __restrict__ res0)
{
    constexpr bool TRA = (MODE==1);
    constexpr int BM = TRA?64:128;
    constexpr int KD = TRA?2048:1024;
    constexpr int WN = TRA?32:64;
    constexpr int NT = WN/16;
    constexpr int AP=40, BP=136;
    constexpr int ASZ=BM*AP, BSZ=32*BP, STRD=2*ASZ+2*BSZ;

    extern __shared__ unsigned short sm[];

    const int tid=threadIdx.x, lane=tid&31, w=tid>>5;
    const int n0=blockIdx.x*128;

    const float* A; const float* Bm; float* C; const float* res=nullptr;
    const float* bs=bias;
    int lda, ldb, ldc, m0; float alpha;
    if constexpr(MODE==0){
        A=A0; lda=DD; Bm=B0; ldb=3*DD; C=C0; ldc=DD; alpha=1.f; m0=blockIdx.y*128;
    } else if constexpr(MODE==1){
        const int z=blockIdx.y, b=z>>4, n=z&15;
        A=A0+(size_t)b*SS*DD+n*64; lda=DD;
        Bm=B0+(size_t)n*DD; ldb=NH*DD;
        C=C0+((size_t)b*DD+n*64)*DD; ldc=DD; alpha=1.f; m0=0;
    } else if constexpr(MODE==3){
        const int z=blockIdx.z;
        A=A0; lda=3*DD; Bm=B0+(size_t)z*DD*DD; ldb=DD;
        C=C0+(size_t)z*DD*DD; ldc=DD; alpha=1.f; m0=blockIdx.y*128;
    } else {
        const int z=blockIdx.z;
        A=A0+(size_t)z*SS*DD; lda=DD; Bm=B0+(size_t)z*DD*DD; ldb=DD;
        C=C0+(size_t)z*SS*DD; ldc=DD; res=res0+(size_t)z*SS*DD;
        bs=bias+(size_t)z*DD; alpha=0.125f; m0=blockIdx.y*128;
    }

    const int wm = TRA?(w&1)*32:(w&3)*32;
    const int wn = TRA?(w>>1)*32:(w>>2)*64;
    const int a_r=lane&15, a_c=(lane>>4)<<3;
    const int b_r=(lane&7)+((lane>>3)&1)*8, b_c=(lane>>4)<<3;

    float acc[2][2*NT][4];
#pragma unroll
    for(int i=0;i<2;++i)
#pragma unroll
        for(int j=0;j<2*NT;++j)
#pragma unroll
            for(int q=0;q<4;++q) acc[i][j][q]=0.f;

    constexpr int NA = TRA?2:4;
    float4 pa[NA], pb[4];

    auto loadA=[&](int k0){
        if constexpr(!TRA){
#pragma unroll
            for(int i=0;i<NA;++i){ int id=i*256+tid, r=id>>3, c=(id&7)*4;
                pa[i]=*(const float4*)(A+(size_t)(m0+r)*lda+k0+c); }
        } else {
#pragma unroll
            for(int i=0;i<NA;++i){ int id=i*256+tid, kr=id>>4, mc=(id&15)*4;
                pa[i]=*(const float4*)(A+(size_t)(k0+kr)*lda+mc); }
        }
    };
    auto loadB=[&](int k0){
#pragma unroll
        for(int i=0;i<4;++i){ int id=i*256+tid, r=id>>5, c=(id&31)*4;
            pb[i]=*(const float4*)(Bm+(size_t)(k0+r)*ldb+n0+c); }
    };
    auto storeT=[&](int buf){
        unsigned short* Ah=sm+buf*STRD;
        unsigned short* Al=Ah+ASZ;
        unsigned short* Bh=sm+buf*STRD+2*ASZ;
        unsigned short* Bl=Bh+BSZ;
        if constexpr(!TRA){
#pragma unroll
            for(int i=0;i<NA;++i){ int id=i*256+tid, r=id>>3, c=(id&7)*4;
                uint32_t h0,l0,h1,l1; split2(pa[i].x,pa[i].y,h0,l0); split2(pa[i].z,pa[i].w,h1,l1);
                *(uint2*)&Ah[r*AP+c]=make_uint2(h0,h1);
                *(uint2*)&Al[r*AP+c]=make_uint2(l0,l1);
            }
        } else {
#pragma unroll
            for(int i=0;i<NA;++i){ int id=i*256+tid, kr=id>>4, mc=(id&15)*4;
                float e[4]={pa[i].x,pa[i].y,pa[i].z,pa[i].w};
#pragma unroll
                for(int j=0;j<4;++j){
                    uint32_t u=__float_as_uint(e[j])&0xffff0000u;
                    Ah[(mc+j)*AP+kr]=(unsigned short)(u>>16);
                    Al[(mc+j)*AP+kr]=bf16_bits(e[j]-__uint_as_float(u));
                }
            }
        }
#pragma unroll
        for(int i=0;i<4;++i){ int id=i*256+tid, r=id>>5, c=(id&31)*4;
            uint32_t h0,l0,h1,l1; split2(pb[i].x,pb[i].y,h0,l0); split2(pb[i].z,pb[i].w,h1,l1);
            *(uint2*)&Bh[r*BP+c]=make_uint2(h0,h1);
            *(uint2*)&Bl[r*BP+c]=make_uint2(l0,l1);
        }
    };
    auto compute=[&](int buf){
        const unsigned short* Ah=sm+buf*STRD;
        const unsigned short* Al=Ah+ASZ;
        const unsigned short* Bh=sm+buf*STRD+2*ASZ;
        const unsigned short* Bl=Bh+BSZ;
#pragma unroll
        for(int kk=0;kk<32;kk+=16){
            uint32_t ah[2][4], al[2][4], bh[NT][4], bl[NT][4];
#pragma unroll
            for(int mt=0;mt<2;++mt){
                const int ao=(wm+mt*16+a_r)*AP+kk+a_c;
                ldm4(ah[mt],&Ah[ao]); ldm4(al[mt],&Al[ao]);
            }
#pragma unroll
            for(int nt=0;nt<NT;++nt){
                const int bo=(kk+b_r)*BP+wn+nt*16+b_c;
                ldm4t(bh[nt],&Bh[bo]); ldm4t(bl[nt],&Bl[bo]);
            }
#pragma unroll
            for(int mt=0;mt<2;++mt)
#pragma unroll
                for(int j=0;j<2*NT;++j){
                    const uint32_t* B1=&bh[j>>1][(j&1)*2];
                    const uint32_t* B2=&bl[j>>1][(j&1)*2];
                    mma16816(acc[mt][j],ah[mt],B1[0],B1[1]);
                    mma16816(acc[mt][j],ah[mt],B2[0],B2[1]);
                    mma16816(acc[mt][j],al[mt],B1[0],B1[1]);
                }
        }
    };

    // prologue: fill buf0, prefetch stage1
    loadA(0); loadB(0);
    storeT(0);
    loadA(32); loadB(32);
    __syncthreads();

    for(int k0=0;k0<KD;k0+=32){
        const int buf=(k0>>5)&1;
        if(k0+32<KD) storeT(buf^1);
        if(k0+64<KD){ loadA(k0+64); loadB(k0+64); }
        compute(buf);
        __syncthreads();
    }

    // epilogue
    const int gid=lane>>2, tig=lane&3;
#pragma unroll
    for(int mt=0;mt<2;++mt)
#pragma unroll
        for(int j=0;j<2*NT;++j){
            const int r0=m0+wm+mt*16+gid;
            const int c=n0+wn+j*8+tig*2;
            float2 v0=make_float2(acc[mt][j][0]*alpha, acc[mt][j][1]*alpha);
            float2 v1=make_float2(acc[mt][j][2]*alpha, acc[mt][j][3]*alpha);
            if constexpr(MODE==0||MODE==2){
                v0.x+=bs[c]; v0.y+=bs[c+1];
                v1.x+=bs[c]; v1.y+=bs[c+1];
            }
            if constexpr(MODE==2){
                const float* rr0=res+(size_t)r0*ldc+c;
                const float* rr1=res+(size_t)(r0+8)*ldc+c;
                v0.x+=rr0[0]; v0.y+=rr0[1];
                v1.x+=rr1[0]; v1.y+=rr1[1];
            }
            *(float2*)(C+(size_t)r0*ldc+c)=v0;
            *(float2*)(C+(size_t)(r0+8)*ldc+c)=v1;
        }
}

// ---------------------------------------------------------------------------
// B2[b,d] = 0.125 * sum_c bq[c] * W2[b,c,d] + b_fc[d]
// ---------------------------------------------------------------------------
__global__ __launch_bounds__(256)
void bias2_kernel(const float* __restrict__ W2, const float* __restrict__ bq,
                  const float* __restrict__ bfc, float* __restrict__ B2)
{
    const int b=blockIdx.y, d=blockIdx.x*256+threadIdx.x;
    const float* Wb=W2+(size_t)b*DD*DD+d;
    float s=0.f;
    for(int c=0;c<DD;++c) s+=bq[c]*Wb[(size_t)c*DD];
    B2[b*DD+d]=0.125f*s+bfc[d];
}

// ---------------------------------------------------------------------------
__global__ __launch_bounds__(256)
void ln_kernel(const float* __restrict__ Y, const float* __restrict__ gamma,
               const float* __restrict__ beta, float* __restrict__ out)
{
    const int row=blockIdx.x, tid=threadIdx.x;
    float4 v=((const float4*)(Y+(size_t)row*DD))[tid];
    __shared__ float sbm[8];
    float s=v.x+v.y+v.z+v.w;
#pragma unroll
    for(int o=16;o;o>>=1) s+=__shfl_xor_sync(0xffffffffu,s,o);
    if((tid&31)==0) sbm[tid>>5]=s;
    __syncthreads();
    float tot=0.f;
#pragma unroll
    for(int i=0;i<8;++i) tot+=sbm[i];
    const float mean=tot*(1.0f/DD);
    __syncthreads();
    const float dx=v.x-mean,dy=v.y-mean,dz=v.z-mean,dw=v.w-mean;
    float ss=dx*dx+dy*dy+dz*dz+dw*dw;
#pragma unroll
    for(int o=16;o;o>>=1) ss+=__shfl_xor_sync(0xffffffffu,ss,o);
    if((tid&31)==0) sbm[tid>>5]=ss;
    __syncthreads();
    float t2=0.f;
#pragma unroll
    for(int i=0;i<8;++i) t2+=sbm[i];
    const float inv=rsqrtf(t2*(1.0f/DD)+1e-5f);
    const float4 g=((const float4*)gamma)[tid], bt=((const float4*)beta)[tid];
    float4 o4;
    o4.x=g.x*dx*inv+bt.x; o4.y=g.y*dy*inv+bt.y; o4.z=g.z*dz*inv+bt.z; o4.w=g.w*dw*inv+bt.w;
    ((float4*)(out+(size_t)row*DD))[tid]=o4;
}

// ---------------------------------------------------------------------------
extern "C" void kernel_launch(void* const* d_in, const int* in_sizes, int n_in,
                              void* d_out, int out_size)
{
    const float* x=(const float*)d_in[0];
    const float* w_qkv=(const float*)d_in[1];
    const float* b_qkv=(const float*)d_in[2];
    const float* w_fc=(const float*)d_in[3];
    const float* b_fc=(const float*)d_in[4];
    const float* gamma=(const float*)d_in[5];
    const float* beta=(const float*)d_in[6];
    float* out=(float*)d_out;

    float *K,*W2,*M3,*B2,*Y;
    cudaGetSymbolAddress((void**)&K, g_K);
    cudaGetSymbolAddress((void**)&W2,g_W2);
    cudaGetSymbolAddress((void**)&M3,g_M3);
    cudaGetSymbolAddress((void**)&B2,g_B2);
    cudaGetSymbolAddress((void**)&Y, g_Y);

    // dynamic smem sizes (bytes): 2 stages of (2*A + 2*B) halfword tiles
    const int smM = 2*(2*128*40 + 2*32*136)*2;   // 75776
    const int smK2= 2*(2*64*40  + 2*32*136)*2;   // 55296
    static int inited=0;
    if(!inited){
        cudaFuncSetAttribute(gemm_u<0>, cudaFuncAttributeMaxDynamicSharedMemorySize, smM);
        cudaFuncSetAttribute(gemm_u<1>, cudaFuncAttributeMaxDynamicSharedMemorySize, smK2);
        cudaFuncSetAttribute(gemm_u<2>, cudaFuncAttributeMaxDynamicSharedMemorySize, smM);
        cudaFuncSetAttribute(gemm_u<3>, cudaFuncAttributeMaxDynamicSharedMemorySize, smM);
        inited=1;
    }

    // K projection: K = x @ w_qkv[:,1024:2048] + b_qkv[1024:2048]
    gemm_u<0><<<dim3(8,32), 256, smM>>>(x, w_qkv+DD, K, b_qkv+DD, nullptr);
    // W2 per head
    gemm_u<1><<<dim3(8,32), 256, smK2>>>(K, w_fc, W2, nullptr, nullptr);
    // combined bias (bq @ W2 term + b_fc)
    bias2_kernel<<<dim3(4,2), 256>>>(W2, b_qkv, b_fc, B2);
    // M3 = Wq @ W2
    gemm_u<3><<<dim3(8,8,2), 256, smM>>>(w_qkv, W2, M3, nullptr, nullptr);
    // Y = 0.125 * x @ M3 + B2 + x
    gemm_u<2><<<dim3(8,16,2), 256, smM>>>(x, M3, Y, B2, x);
    // LayerNorm
    ln_kernel<<<BB*SS, 256>>>(Y, gamma, beta, out);
}